// round 3
// baseline (speedup 1.0000x reference)
#include <cuda_runtime.h>
#include <cstdint>
#include <math.h>

#define LSTMN 256
#define CLSZ  16
#define ROWS  64      // rows of w_ih/w_hh per CTA  (16*64 = 1024)
#define W12R  16      // rows of w1/w2 per CTA      (16*16 = 256)
#define NTH   256
#define NBLK  6

struct __align__(16) Smem {
    float wih[ROWS * LSTMN];   // 64 KB
    float whh[ROWS * LSTMN];   // 64 KB
    float w1p[W12R * LSTMN];   // 16 KB
    float w2p[W12R * LSTMN];   // 16 KB
    float x[LSTMN];
    float h[LSTMN];
    float c[LSTMN];
    float enc0[LSTMN];
    float v[LSTMN];
    float g[ROWS];
    float bsum[ROWS];
    float aw1[7][LSTMN];       // anchors_w1, replicated
    float anc[7][LSTMN];       // anchors, replicated
    float w2h[LSTMN];          // w2 @ h, replicated
    float red[6 * 8];
    float lp, ent;
    int   idx;
};

__device__ float g_lp[NBLK];
__device__ float g_ent[NBLK];

// ---------------- low-level helpers ----------------

__device__ __forceinline__ uint32_t sm_u32(const void* p) {
    return (uint32_t)__cvta_generic_to_shared(p);
}
__device__ __forceinline__ uint32_t ctarank() {
    uint32_t r; asm("mov.u32 %0, %%cluster_ctarank;" : "=r"(r)); return r;
}
__device__ __forceinline__ float ds_ld(uint32_t laddr, uint32_t rank) {
    uint32_t ra; float val;
    asm volatile("mapa.shared::cluster.u32 %0, %1, %2;" : "=r"(ra) : "r"(laddr), "r"(rank));
    asm volatile("ld.shared::cluster.f32 %0, [%1];" : "=f"(val) : "r"(ra));
    return val;
}
__device__ __forceinline__ void ds_st(uint32_t laddr, uint32_t rank, float val) {
    uint32_t ra;
    asm volatile("mapa.shared::cluster.u32 %0, %1, %2;" : "=r"(ra) : "r"(laddr), "r"(rank));
    asm volatile("st.shared::cluster.f32 [%0], %1;" :: "r"(ra), "f"(val) : "memory");
}
__device__ __forceinline__ void csync() {
    asm volatile("barrier.cluster.arrive.aligned;" ::: "memory");
    asm volatile("barrier.cluster.wait.aligned;" ::: "memory");
}

// threefry2x32, 20 rounds — exact JAX semantics
__device__ __forceinline__ uint2 tf2x32(uint2 key, uint2 ctr) {
    uint32_t ks0 = key.x, ks1 = key.y, ks2 = ks0 ^ ks1 ^ 0x1BD11BDAu;
    uint32_t x0 = ctr.x + ks0, x1 = ctr.y + ks1;
#define TF_RND(r) { x0 += x1; x1 = (x1 << (r)) | (x1 >> (32 - (r))); x1 ^= x0; }
    TF_RND(13) TF_RND(15) TF_RND(26) TF_RND(6)  x0 += ks1; x1 += ks2 + 1u;
    TF_RND(17) TF_RND(29) TF_RND(16) TF_RND(24) x0 += ks2; x1 += ks0 + 2u;
    TF_RND(13) TF_RND(15) TF_RND(26) TF_RND(6)  x0 += ks0; x1 += ks1 + 3u;
    TF_RND(17) TF_RND(29) TF_RND(16) TF_RND(24) x0 += ks1; x1 += ks2 + 4u;
    TF_RND(13) TF_RND(15) TF_RND(26) TF_RND(6)  x0 += ks2; x1 += ks0 + 5u;
#undef TF_RND
    return make_uint2(x0, x1);
}

// accurate tanh/sigmoid built on expf (robust under fast-math)
__device__ __forceinline__ float my_tanh(float xv) {
    float ax = fabsf(xv);
    float t = expf(-2.0f * ax);
    float r = (1.0f - t) / (1.0f + t);
    return copysignf(r, xv);
}
__device__ __forceinline__ float my_sig(float xv) {
    return 1.0f / (1.0f + expf(-xv));
}

// ---------------- one LSTM cell + fused w1/w2 slice matvec ----------------
// mode 0: compute w2 slice of (w2 @ h_new), broadcast into every CTA's w2h
// mode 1: compute w1 slice of (w1 @ h_new), broadcast into aw1[slot]
//         (slot==0 additionally fills aw1[1] — first two layers are identical)
__device__ __forceinline__ void do_cell(Smem* s, int rank, int tid, int mode, int slot) {
    __syncthreads();
    const int lane = tid & 31, wrp = tid >> 5;

    // ---- G phase: 64 gate rows per CTA; 1 warp handles 8 rows ----
    {
        const float4* XV = (const float4*)s->x;
        const float4* HV = (const float4*)s->h;
        float4 xa = XV[lane], xb = XV[lane + 32];
        float4 ha = HV[lane], hb = HV[lane + 32];
#pragma unroll
        for (int rr = 0; rr < 8; rr++) {
            int r = wrp * 8 + rr;
            const float4* wi = (const float4*)(s->wih + r * LSTMN);
            const float4* wh = (const float4*)(s->whh + r * LSTMN);
            float4 a = wi[lane], b4 = wi[lane + 32];
            float acc = a.x * xa.x + a.y * xa.y + a.z * xa.z + a.w * xa.w
                      + b4.x * xb.x + b4.y * xb.y + b4.z * xb.z + b4.w * xb.w;
            a = wh[lane]; b4 = wh[lane + 32];
            acc += a.x * ha.x + a.y * ha.y + a.z * ha.z + a.w * ha.w
                 + b4.x * hb.x + b4.y * hb.y + b4.z * hb.z + b4.w * hb.w;
            acc += __shfl_xor_sync(0xffffffffu, acc, 16);
            acc += __shfl_xor_sync(0xffffffffu, acc, 8);
            acc += __shfl_xor_sync(0xffffffffu, acc, 4);
            acc += __shfl_xor_sync(0xffffffffu, acc, 2);
            acc += __shfl_xor_sync(0xffffffffu, acc, 1);
            if (lane == 0) s->g[r] = acc + s->bsum[r];
        }
    }
    csync();

    // ---- H phase: every CTA reconstructs full h,c (replicated) via DSMEM ----
    {
        int u = tid;
        uint32_t ga = sm_u32(&s->g[u & 63]);
        uint32_t ci = (uint32_t)(u >> 6);
        float gi = ds_ld(ga, ci);
        float gf = ds_ld(ga, ci + 4);
        float gg = ds_ld(ga, ci + 8);
        float go = ds_ld(ga, ci + 12);
        float cn = my_sig(gf) * s->c[u] + my_sig(gi) * my_tanh(gg);
        float hn = my_sig(go) * my_tanh(cn);
        s->c[u] = cn;
        s->h[u] = hn;
    }
    __syncthreads();

    // ---- fused w1/w2 slice matvec + cluster broadcast ----
    {
        int rl = tid >> 4;     // 0..15: local row within slice
        int seg = tid & 15;    // 16 lanes cooperate per row
        const float* wr = (mode == 0 ? s->w2p : s->w1p) + rl * LSTMN;
        float acc = 0.0f;
#pragma unroll
        for (int k = 0; k < 16; k++) {
            int id = k * 16 + seg;
            acc = fmaf(wr[id], s->h[id], acc);
        }
        acc += __shfl_xor_sync(0xffffffffu, acc, 8);
        acc += __shfl_xor_sync(0xffffffffu, acc, 4);
        acc += __shfl_xor_sync(0xffffffffu, acc, 2);
        acc += __shfl_xor_sync(0xffffffffu, acc, 1);
        int grow = rank * W12R + rl;
        if (mode == 0) {
            ds_st(sm_u32(&s->w2h[grow]), (uint32_t)seg, acc);
        } else {
            ds_st(sm_u32(&s->aw1[slot][grow]), (uint32_t)seg, acc);
            if (slot == 0) ds_st(sm_u32(&s->aw1[1][grow]), (uint32_t)seg, acc);
        }
    }
    csync();
}

// ---------------- sampling (replicated per CTA; no cluster syncs) ----------------
__device__ __forceinline__ void do_sample(Smem* s, int tid, int layer, uint2 bkey,
                                          int step, float* out, int b, int rank) {
    const int lane = tid & 31, wrp = tid >> 5;
    float w2h_t = s->w2h[tid];
    float vt = s->v[tid];
    for (int l = 0; l < layer; l++) {
        float val = my_tanh(s->aw1[l][tid] + w2h_t) * vt;
        val += __shfl_xor_sync(0xffffffffu, val, 16);
        val += __shfl_xor_sync(0xffffffffu, val, 8);
        val += __shfl_xor_sync(0xffffffffu, val, 4);
        val += __shfl_xor_sync(0xffffffffu, val, 2);
        val += __shfl_xor_sync(0xffffffffu, val, 1);
        if (lane == 0) s->red[l * 8 + wrp] = val;
    }
    __syncthreads();
    if (tid == 0) {
        float logits[6];
        for (int l = 0; l < layer; l++) {
            float sum = 0.0f;
            for (int j = 0; j < 8; j++) sum += s->red[l * 8 + j];
            logits[l] = 1.1f * my_tanh(sum / 5.0f);
        }
        // skey = fold_in(bkey, step)   (fold_in is unchanged by partitionable flag)
        uint2 skey = tf2x32(bkey, make_uint2(0u, (uint32_t)step));
        // JAX partitionable threefry random_bits (jax_threefry_partitionable=True,
        // the modern default): one independent threefry block per element with
        // 64-bit iota counter (hi=0, lo=i); 32-bit output = hi_word ^ lo_word.
        const float TINYF = 1.17549435e-38f;
        int n = layer;
        int best = 0; float bestv = -1e38f;
        for (int i = 0; i < n; i++) {
            uint2 o = tf2x32(skey, make_uint2(0u, (uint32_t)i));
            uint32_t bits = o.x ^ o.y;
            float u = __uint_as_float((bits >> 9) | 0x3f800000u) - 1.0f;
            float up = fmaxf(TINYF, u + TINYF);
            float gmb = (float)(-log(-log((double)up)));
            float pert = gmb + logits[i];
            if (pert > bestv) { bestv = pert; best = i; }
        }
        // log-softmax / entropy in double (1e-3 tolerance has plenty of slack)
        float mx = logits[0];
        for (int i = 1; i < n; i++) mx = fmaxf(mx, logits[i]);
        double se = 0.0;
        for (int i = 0; i < n; i++) se += exp((double)logits[i] - (double)mx);
        double lse = log(se);
        double lp_step = -((double)logits[best] - (double)mx - lse);
        double ent = 0.0;
        for (int i = 0; i < n; i++) {
            double ls = (double)logits[i] - (double)mx - lse;
            ent -= ls * exp(ls);
        }
        s->lp += (float)lp_step;
        s->ent += (float)ent;
        s->idx = best;
        if (rank == 0) out[b * 10 + step] = (float)best;
    }
    __syncthreads();
    int id = s->idx;
    s->x[tid] = s->anc[id][tid];   // inputs = anchors[index]
}

// ---------------- main kernel: one 16-CTA cluster per block ----------------
__global__ void __launch_bounds__(NTH, 1) ctrl_kernel(
    const float* __restrict__ enc_w, const float* __restrict__ w_ih,
    const float* __restrict__ w_hh, const float* __restrict__ b_ih,
    const float* __restrict__ b_hh, const float* __restrict__ w1,
    const float* __restrict__ w2, const float* __restrict__ v,
    float* __restrict__ out)
{
    extern __shared__ char smraw[];
    Smem* s = (Smem*)smraw;
    const int tid = threadIdx.x;
    const int rank = (int)ctarank();
    const int b = blockIdx.y;

    // ---- prologue: stage weight slices + state into smem ----
    {
        const float4* src = (const float4*)(w_ih + (size_t)rank * ROWS * LSTMN);
        float4* dst = (float4*)s->wih;
        for (int i = tid; i < ROWS * LSTMN / 4; i += NTH) dst[i] = src[i];
        src = (const float4*)(w_hh + (size_t)rank * ROWS * LSTMN);
        dst = (float4*)s->whh;
        for (int i = tid; i < ROWS * LSTMN / 4; i += NTH) dst[i] = src[i];
        src = (const float4*)(w1 + (size_t)rank * W12R * LSTMN);
        dst = (float4*)s->w1p;
        for (int i = tid; i < W12R * LSTMN / 4; i += NTH) dst[i] = src[i];
        src = (const float4*)(w2 + (size_t)rank * W12R * LSTMN);
        dst = (float4*)s->w2p;
        for (int i = tid; i < W12R * LSTMN / 4; i += NTH) dst[i] = src[i];
        if (tid < ROWS)
            s->bsum[tid] = b_ih[rank * ROWS + tid] + b_hh[rank * ROWS + tid];
        float e = enc_w[tid];          // enc_w row 0
        s->enc0[tid] = e;
        s->x[tid] = e;
        s->v[tid] = v[tid];
        s->h[tid] = 0.0f;
        s->c[tid] = 0.0f;
        s->anc[0][tid] = 0.0f;
        s->anc[1][tid] = 0.0f;
        if (tid == 0) { s->lp = 0.0f; s->ent = 0.0f; }
    }

    const uint2 key42 = make_uint2(0u, 42u);
    const uint2 bkey = tf2x32(key42, make_uint2(0u, (uint32_t)b));

    // first two "layers" are identical cells with zero state: compute once,
    // fill aw1[0] and aw1[1]; anchors[0]=anchors[1]=0
    do_cell(s, rank, tid, 1, 0);

    int step = 0;
#pragma unroll 1
    for (int layer = 2; layer <= 6; layer++) {
#pragma unroll 1
        for (int rep = 0; rep < 2; rep++) {
            do_cell(s, rank, tid, 0, 0);
            do_sample(s, tid, layer, bkey, step, out, b, rank);
            step++;
        }
        do_cell(s, rank, tid, 1, layer);   // anchor cell
        s->anc[layer][tid] = s->h[tid];
        s->x[tid] = s->enc0[tid];          // inputs = enc_w[0]
    }

    if (rank == 0) {
        if (tid == 0) { g_lp[b] = s->lp; g_ent[b] = s->ent; }
        if (b == NBLK - 1) {
            out[62 + tid] = s->c[tid];
            out[62 + LSTMN + tid] = s->h[tid];
        }
    }
}

// deterministic cross-block scalar reduction (fixed order)
__global__ void fin_kernel(float* __restrict__ out) {
    float lp = 0.0f, ent = 0.0f;
    for (int b = 0; b < NBLK; b++) { lp += g_lp[b]; ent += g_ent[b]; }
    out[60] = lp;
    out[61] = ent;
}

extern "C" void kernel_launch(void* const* d_in, const int* in_sizes, int n_in,
                              void* d_out, int out_size) {
    const float* enc_w = (const float*)d_in[0];
    const float* w_ih  = (const float*)d_in[1];
    const float* w_hh  = (const float*)d_in[2];
    const float* b_ih  = (const float*)d_in[3];
    const float* b_hh  = (const float*)d_in[4];
    const float* w1    = (const float*)d_in[5];
    const float* w2    = (const float*)d_in[6];
    const float* v     = (const float*)d_in[7];
    float* out = (float*)d_out;

    cudaFuncSetAttribute(ctrl_kernel,
                         cudaFuncAttributeMaxDynamicSharedMemorySize,
                         (int)sizeof(Smem));
    cudaFuncSetAttribute(ctrl_kernel,
                         cudaFuncAttributeNonPortableClusterSizeAllowed, 1);

    cudaLaunchConfig_t cfg = {};
    cfg.gridDim = dim3(CLSZ, NBLK, 1);
    cfg.blockDim = dim3(NTH, 1, 1);
    cfg.dynamicSmemBytes = sizeof(Smem);
    cfg.stream = 0;
    cudaLaunchAttribute at[1];
    at[0].id = cudaLaunchAttributeClusterDimension;
    at[0].val.clusterDim.x = CLSZ;
    at[0].val.clusterDim.y = 1;
    at[0].val.clusterDim.z = 1;
    cfg.attrs = at;
    cfg.numAttrs = 1;

    cudaLaunchKernelEx(&cfg, ctrl_kernel,
                       enc_w, w_ih, w_hh, b_ih, b_hh, w1, w2, v, out);
    fin_kernel<<<1, 1>>>(out);
}

// round 4
// speedup vs baseline: 2.7857x; 2.7857x over previous
#include <cuda_runtime.h>
#include <cstdint>
#include <math.h>

#define LSTMN 256
#define CLSZ  16
#define ROWS  64      // rows of w_ih/w_hh per CTA  (16*64 = 1024)
#define W12R  16      // rows of w1/w2 per CTA      (16*16 = 256)
#define NTH   256
#define NBLK  6

struct __align__(16) Smem {
    float wih[ROWS * LSTMN];   // 64 KB
    float whh[ROWS * LSTMN];   // 64 KB
    float w1p[W12R * LSTMN];   // 16 KB
    float w2p[W12R * LSTMN];   // 16 KB
    float x[LSTMN];
    float h[LSTMN];
    float c[LSTMN];
    float enc0[LSTMN];
    float v[LSTMN];
    float g[ROWS];
    float bsum[ROWS];
    float aw1[7][LSTMN];       // anchors_w1, replicated
    float anc[7][LSTMN];       // anchors, replicated
    float w2h[LSTMN];          // w2 @ h, replicated
    float red[6 * 8];
    float lp, ent;
    int   idx;
};

__device__ float g_lp[NBLK];
__device__ float g_ent[NBLK];

// ---------------- low-level helpers ----------------

__device__ __forceinline__ uint32_t sm_u32(const void* p) {
    return (uint32_t)__cvta_generic_to_shared(p);
}
__device__ __forceinline__ uint32_t ctarank() {
    uint32_t r; asm("mov.u32 %0, %%cluster_ctarank;" : "=r"(r)); return r;
}
__device__ __forceinline__ float ds_ld(uint32_t laddr, uint32_t rank) {
    uint32_t ra; float val;
    asm volatile("mapa.shared::cluster.u32 %0, %1, %2;" : "=r"(ra) : "r"(laddr), "r"(rank));
    asm volatile("ld.shared::cluster.f32 %0, [%1];" : "=f"(val) : "r"(ra));
    return val;
}
__device__ __forceinline__ void ds_st(uint32_t laddr, uint32_t rank, float val) {
    uint32_t ra;
    asm volatile("mapa.shared::cluster.u32 %0, %1, %2;" : "=r"(ra) : "r"(laddr), "r"(rank));
    asm volatile("st.shared::cluster.f32 [%0], %1;" :: "r"(ra), "f"(val) : "memory");
}
__device__ __forceinline__ void csync() {
    asm volatile("barrier.cluster.arrive.aligned;" ::: "memory");
    asm volatile("barrier.cluster.wait.aligned;" ::: "memory");
}

// threefry2x32, 20 rounds — exact JAX semantics
__device__ __forceinline__ uint2 tf2x32(uint2 key, uint2 ctr) {
    uint32_t ks0 = key.x, ks1 = key.y, ks2 = ks0 ^ ks1 ^ 0x1BD11BDAu;
    uint32_t x0 = ctr.x + ks0, x1 = ctr.y + ks1;
#define TF_RND(r) { x0 += x1; x1 = (x1 << (r)) | (x1 >> (32 - (r))); x1 ^= x0; }
    TF_RND(13) TF_RND(15) TF_RND(26) TF_RND(6)  x0 += ks1; x1 += ks2 + 1u;
    TF_RND(17) TF_RND(29) TF_RND(16) TF_RND(24) x0 += ks2; x1 += ks0 + 2u;
    TF_RND(13) TF_RND(15) TF_RND(26) TF_RND(6)  x0 += ks0; x1 += ks1 + 3u;
    TF_RND(17) TF_RND(29) TF_RND(16) TF_RND(24) x0 += ks1; x1 += ks2 + 4u;
    TF_RND(13) TF_RND(15) TF_RND(26) TF_RND(6)  x0 += ks2; x1 += ks0 + 5u;
#undef TF_RND
    return make_uint2(x0, x1);
}

// accurate tanh/sigmoid built on expf (robust under fast-math)
__device__ __forceinline__ float my_tanh(float xv) {
    float ax = fabsf(xv);
    float t = expf(-2.0f * ax);
    float r = (1.0f - t) / (1.0f + t);
    return copysignf(r, xv);
}
__device__ __forceinline__ float my_sig(float xv) {
    return 1.0f / (1.0f + expf(-xv));
}

// ---------------- one LSTM cell + fused w1/w2 slice matvec ----------------
// mode 0: compute w2 slice of (w2 @ h_new), broadcast into every CTA's w2h
// mode 1: compute w1 slice of (w1 @ h_new), broadcast into aw1[slot]
//         (slot==0 additionally fills aw1[1] — first two layers are identical)
__device__ __forceinline__ void do_cell(Smem* s, int rank, int tid, int mode, int slot) {
    __syncthreads();
    const int lane = tid & 31, wrp = tid >> 5;

    // ---- G phase: 64 gate rows per CTA; 1 warp handles 8 rows ----
    {
        const float4* XV = (const float4*)s->x;
        const float4* HV = (const float4*)s->h;
        float4 xa = XV[lane], xb = XV[lane + 32];
        float4 ha = HV[lane], hb = HV[lane + 32];
#pragma unroll
        for (int rr = 0; rr < 8; rr++) {
            int r = wrp * 8 + rr;
            const float4* wi = (const float4*)(s->wih + r * LSTMN);
            const float4* wh = (const float4*)(s->whh + r * LSTMN);
            float4 a = wi[lane], b4 = wi[lane + 32];
            float acc = a.x * xa.x + a.y * xa.y + a.z * xa.z + a.w * xa.w
                      + b4.x * xb.x + b4.y * xb.y + b4.z * xb.z + b4.w * xb.w;
            a = wh[lane]; b4 = wh[lane + 32];
            acc += a.x * ha.x + a.y * ha.y + a.z * ha.z + a.w * ha.w
                 + b4.x * hb.x + b4.y * hb.y + b4.z * hb.z + b4.w * hb.w;
            acc += __shfl_xor_sync(0xffffffffu, acc, 16);
            acc += __shfl_xor_sync(0xffffffffu, acc, 8);
            acc += __shfl_xor_sync(0xffffffffu, acc, 4);
            acc += __shfl_xor_sync(0xffffffffu, acc, 2);
            acc += __shfl_xor_sync(0xffffffffu, acc, 1);
            if (lane == 0) s->g[r] = acc + s->bsum[r];
        }
    }
    csync();

    // ---- H phase: every CTA reconstructs full h,c (replicated) via DSMEM ----
    {
        int u = tid;
        uint32_t ga = sm_u32(&s->g[u & 63]);
        uint32_t ci = (uint32_t)(u >> 6);
        float gi = ds_ld(ga, ci);
        float gf = ds_ld(ga, ci + 4);
        float gg = ds_ld(ga, ci + 8);
        float go = ds_ld(ga, ci + 12);
        float cn = my_sig(gf) * s->c[u] + my_sig(gi) * my_tanh(gg);
        float hn = my_sig(go) * my_tanh(cn);
        s->c[u] = cn;
        s->h[u] = hn;
    }
    __syncthreads();

    // ---- fused w1/w2 slice matvec + cluster broadcast ----
    {
        int rl = tid >> 4;     // 0..15: local row within slice
        int seg = tid & 15;    // 16 lanes cooperate per row
        const float* wr = (mode == 0 ? s->w2p : s->w1p) + rl * LSTMN;
        float acc = 0.0f;
#pragma unroll
        for (int k = 0; k < 16; k++) {
            int id = k * 16 + seg;
            acc = fmaf(wr[id], s->h[id], acc);
        }
        acc += __shfl_xor_sync(0xffffffffu, acc, 8);
        acc += __shfl_xor_sync(0xffffffffu, acc, 4);
        acc += __shfl_xor_sync(0xffffffffu, acc, 2);
        acc += __shfl_xor_sync(0xffffffffu, acc, 1);
        int grow = rank * W12R + rl;
        if (mode == 0) {
            ds_st(sm_u32(&s->w2h[grow]), (uint32_t)seg, acc);
        } else {
            ds_st(sm_u32(&s->aw1[slot][grow]), (uint32_t)seg, acc);
            if (slot == 0) ds_st(sm_u32(&s->aw1[1][grow]), (uint32_t)seg, acc);
        }
    }
    csync();
}

// ---------------- sampling (replicated per CTA; no cluster syncs) ----------------
// All math in fp32 (matches the JAX f32 pipeline); candidates parallel on warp 0.
__device__ __forceinline__ void do_sample(Smem* s, int tid, int layer, uint2 bkey,
                                          int step, float* out, int b, int rank) {
    const int lane = tid & 31, wrp = tid >> 5;
    float w2h_t = s->w2h[tid];
    float vt = s->v[tid];
    for (int l = 0; l < layer; l++) {
        float val = my_tanh(s->aw1[l][tid] + w2h_t) * vt;
        val += __shfl_xor_sync(0xffffffffu, val, 16);
        val += __shfl_xor_sync(0xffffffffu, val, 8);
        val += __shfl_xor_sync(0xffffffffu, val, 4);
        val += __shfl_xor_sync(0xffffffffu, val, 2);
        val += __shfl_xor_sync(0xffffffffu, val, 1);
        if (lane == 0) s->red[l * 8 + wrp] = val;
    }
    __syncthreads();
    if (wrp == 0) {
        const bool act = lane < layer;
        float logit = 0.0f;
        if (act) {
            float sum = 0.0f;
#pragma unroll
            for (int j = 0; j < 8; j++) sum += s->red[lane * 8 + j];
            logit = 1.1f * my_tanh(sum * 0.2f);
        }
        // skey = fold_in(bkey, step); partitionable threefry:
        // bits[i] = hi ^ lo of threefry(skey, (0, i))
        uint2 skey = tf2x32(bkey, make_uint2(0u, (uint32_t)step));
        float pert = -1e38f;
        if (act) {
            uint2 o = tf2x32(skey, make_uint2(0u, (uint32_t)lane));
            uint32_t bits = o.x ^ o.y;
            float u = __uint_as_float((bits >> 9) | 0x3f800000u) - 1.0f;
            const float TINYF = 1.17549435e-38f;
            float up = fmaxf(TINYF, u + TINYF);
            float gmb = -logf(-logf(up));     // f32, same as JAX
            pert = gmb + logit;
        }
        // warp argmax, lowest-index tiebreak
        float bp = pert; int bi = act ? lane : 64;
#pragma unroll
        for (int off = 16; off; off >>= 1) {
            float op = __shfl_xor_sync(0xffffffffu, bp, off);
            int oi = __shfl_xor_sync(0xffffffffu, bi, off);
            if (op > bp || (op == bp && oi < bi)) { bp = op; bi = oi; }
        }
        // f32 log-softmax + entropy
        float lm = act ? logit : -1e38f;
#pragma unroll
        for (int off = 16; off; off >>= 1)
            lm = fmaxf(lm, __shfl_xor_sync(0xffffffffu, lm, off));
        float ex = act ? expf(logit - lm) : 0.0f;
        float se = ex;
#pragma unroll
        for (int off = 16; off; off >>= 1)
            se += __shfl_xor_sync(0xffffffffu, se, off);
        float lse = logf(se);
        float ls = logit - lm - lse;
        float ls_best = __shfl_sync(0xffffffffu, ls, bi);
        float ec = act ? (-ls * expf(ls)) : 0.0f;
#pragma unroll
        for (int off = 16; off; off >>= 1)
            ec += __shfl_xor_sync(0xffffffffu, ec, off);
        if (lane == 0) {
            s->lp += -ls_best;
            s->ent += ec;
            s->idx = bi;
            if (rank == 0) out[b * 10 + step] = (float)bi;
        }
    }
    __syncthreads();
    s->x[tid] = s->anc[s->idx][tid];   // inputs = anchors[index]
}

// ---------------- main kernel: one 16-CTA cluster per block ----------------
__global__ void __launch_bounds__(NTH, 1) ctrl_kernel(
    const float* __restrict__ enc_w, const float* __restrict__ w_ih,
    const float* __restrict__ w_hh, const float* __restrict__ b_ih,
    const float* __restrict__ b_hh, const float* __restrict__ w1,
    const float* __restrict__ w2, const float* __restrict__ v,
    float* __restrict__ out)
{
    extern __shared__ char smraw[];
    Smem* s = (Smem*)smraw;
    const int tid = threadIdx.x;
    const int rank = (int)ctarank();
    const int b = blockIdx.y;

    // ---- prologue: stage weight slices + state into smem ----
    {
        const float4* src = (const float4*)(w_ih + (size_t)rank * ROWS * LSTMN);
        float4* dst = (float4*)s->wih;
        for (int i = tid; i < ROWS * LSTMN / 4; i += NTH) dst[i] = src[i];
        src = (const float4*)(w_hh + (size_t)rank * ROWS * LSTMN);
        dst = (float4*)s->whh;
        for (int i = tid; i < ROWS * LSTMN / 4; i += NTH) dst[i] = src[i];
        src = (const float4*)(w1 + (size_t)rank * W12R * LSTMN);
        dst = (float4*)s->w1p;
        for (int i = tid; i < W12R * LSTMN / 4; i += NTH) dst[i] = src[i];
        src = (const float4*)(w2 + (size_t)rank * W12R * LSTMN);
        dst = (float4*)s->w2p;
        for (int i = tid; i < W12R * LSTMN / 4; i += NTH) dst[i] = src[i];
        if (tid < ROWS)
            s->bsum[tid] = b_ih[rank * ROWS + tid] + b_hh[rank * ROWS + tid];
        float e = enc_w[tid];          // enc_w row 0
        s->enc0[tid] = e;
        s->x[tid] = e;
        s->v[tid] = v[tid];
        s->h[tid] = 0.0f;
        s->c[tid] = 0.0f;
        s->anc[0][tid] = 0.0f;
        s->anc[1][tid] = 0.0f;
        if (tid == 0) { s->lp = 0.0f; s->ent = 0.0f; }
    }

    const uint2 key42 = make_uint2(0u, 42u);
    const uint2 bkey = tf2x32(key42, make_uint2(0u, (uint32_t)b));

    // first two "layers" are identical cells with zero state: compute once,
    // fill aw1[0] and aw1[1]; anchors[0]=anchors[1]=0
    do_cell(s, rank, tid, 1, 0);

    int step = 0;
#pragma unroll 1
    for (int layer = 2; layer <= 6; layer++) {
#pragma unroll 1
        for (int rep = 0; rep < 2; rep++) {
            do_cell(s, rank, tid, 0, 0);
            do_sample(s, tid, layer, bkey, step, out, b, rank);
            step++;
        }
        do_cell(s, rank, tid, 1, layer);   // anchor cell
        s->anc[layer][tid] = s->h[tid];
        s->x[tid] = s->enc0[tid];          // inputs = enc_w[0]
    }

    if (rank == 0) {
        if (tid == 0) { g_lp[b] = s->lp; g_ent[b] = s->ent; }
        if (b == NBLK - 1) {
            out[62 + tid] = s->c[tid];
            out[62 + LSTMN + tid] = s->h[tid];
        }
    }
}

// deterministic cross-block scalar reduction (fixed order)
__global__ void fin_kernel(float* __restrict__ out) {
    float lp = 0.0f, ent = 0.0f;
    for (int b = 0; b < NBLK; b++) { lp += g_lp[b]; ent += g_ent[b]; }
    out[60] = lp;
    out[61] = ent;
}

extern "C" void kernel_launch(void* const* d_in, const int* in_sizes, int n_in,
                              void* d_out, int out_size) {
    const float* enc_w = (const float*)d_in[0];
    const float* w_ih  = (const float*)d_in[1];
    const float* w_hh  = (const float*)d_in[2];
    const float* b_ih  = (const float*)d_in[3];
    const float* b_hh  = (const float*)d_in[4];
    const float* w1    = (const float*)d_in[5];
    const float* w2    = (const float*)d_in[6];
    const float* v     = (const float*)d_in[7];
    float* out = (float*)d_out;

    cudaFuncSetAttribute(ctrl_kernel,
                         cudaFuncAttributeMaxDynamicSharedMemorySize,
                         (int)sizeof(Smem));
    cudaFuncSetAttribute(ctrl_kernel,
                         cudaFuncAttributeNonPortableClusterSizeAllowed, 1);

    cudaLaunchConfig_t cfg = {};
    cfg.gridDim = dim3(CLSZ, NBLK, 1);
    cfg.blockDim = dim3(NTH, 1, 1);
    cfg.dynamicSmemBytes = sizeof(Smem);
    cfg.stream = 0;
    cudaLaunchAttribute at[1];
    at[0].id = cudaLaunchAttributeClusterDimension;
    at[0].val.clusterDim.x = CLSZ;
    at[0].val.clusterDim.y = 1;
    at[0].val.clusterDim.z = 1;
    cfg.attrs = at;
    cfg.numAttrs = 1;

    cudaLaunchKernelEx(&cfg, ctrl_kernel,
                       enc_w, w_ih, w_hh, b_ih, b_hh, w1, w2, v, out);
    fin_kernel<<<1, 1>>>(out);
}

// round 6
// speedup vs baseline: 3.2162x; 1.1546x over previous
#include <cuda_runtime.h>
#include <cstdint>
#include <math.h>

#define LSTMN 256
#define CLSZ  16
#define NTH   256
#define NBLK  6

struct __align__(16) Smem {
    float wih[64 * 256];     // 64 KB  rows: gate q, elems [rank*16, rank*16+16)
    float whh[64 * 256];     // 64 KB
    float w1c[256 * 16];     // 16 KB  w1 columns [rank*16, rank*16+16)
    float w2c[256 * 16];     // 16 KB  w2 columns
    float x[256], h[256], enc0[256], v[256];
    float anc[6][256];       // anchors 0..5 (anchor 6 is never consumed)
    float g[64], bsum[64];
    float hseg[16], c16[16];
    float pw1[256];          // partial w1 @ h_seg
    float pw2[256];          // partial w2 @ h_seg
    float my_aw1[128];       // this CTA's (layer,half) slice of anchors_w1
    float red[16];           // [0..11]: logit partials (2 per layer); [12..15]: temp
    float lp, ent;
    int   idx;
};

__device__ float g_lp[NBLK];
__device__ float g_ent[NBLK];
__device__ int   g_count;

// ---------------- low-level helpers ----------------

__device__ __forceinline__ uint32_t sm_u32(const void* p) {
    return (uint32_t)__cvta_generic_to_shared(p);
}
__device__ __forceinline__ uint32_t ctarank() {
    uint32_t r; asm("mov.u32 %0, %%cluster_ctarank;" : "=r"(r)); return r;
}
__device__ __forceinline__ float ds_ld(uint32_t laddr, uint32_t rank) {
    uint32_t ra; float val;
    asm volatile("mapa.shared::cluster.u32 %0, %1, %2;" : "=r"(ra) : "r"(laddr), "r"(rank));
    asm volatile("ld.shared::cluster.f32 %0, [%1];" : "=f"(val) : "r"(ra));
    return val;
}
__device__ __forceinline__ void ds_st(uint32_t laddr, uint32_t rank, float val) {
    uint32_t ra;
    asm volatile("mapa.shared::cluster.u32 %0, %1, %2;" : "=r"(ra) : "r"(laddr), "r"(rank));
    asm volatile("st.shared::cluster.f32 [%0], %1;" :: "r"(ra), "f"(val) : "memory");
}
__device__ __forceinline__ void csync() {
    asm volatile("barrier.cluster.arrive.aligned;" ::: "memory");
    asm volatile("barrier.cluster.wait.aligned;" ::: "memory");
}

// threefry2x32, 20 rounds — exact JAX semantics
__device__ __forceinline__ uint2 tf2x32(uint2 key, uint2 ctr) {
    uint32_t ks0 = key.x, ks1 = key.y, ks2 = ks0 ^ ks1 ^ 0x1BD11BDAu;
    uint32_t x0 = ctr.x + ks0, x1 = ctr.y + ks1;
#define TF_RND(r) { x0 += x1; x1 = (x1 << (r)) | (x1 >> (32 - (r))); x1 ^= x0; }
    TF_RND(13) TF_RND(15) TF_RND(26) TF_RND(6)  x0 += ks1; x1 += ks2 + 1u;
    TF_RND(17) TF_RND(29) TF_RND(16) TF_RND(24) x0 += ks2; x1 += ks0 + 2u;
    TF_RND(13) TF_RND(15) TF_RND(26) TF_RND(6)  x0 += ks0; x1 += ks1 + 3u;
    TF_RND(17) TF_RND(29) TF_RND(16) TF_RND(24) x0 += ks1; x1 += ks2 + 4u;
    TF_RND(13) TF_RND(15) TF_RND(26) TF_RND(6)  x0 += ks2; x1 += ks0 + 5u;
#undef TF_RND
    return make_uint2(x0, x1);
}

__device__ __forceinline__ float my_tanh(float xv) {
    float ax = fabsf(xv);
    float t = expf(-2.0f * ax);
    float r = (1.0f - t) / (1.0f + t);
    return copysignf(r, xv);
}
__device__ __forceinline__ float my_sig(float xv) {
    return 1.0f / (1.0f + expf(-xv));
}

// ---------------- one LSTM cell ----------------
// kind 0: sample cell  (partial = w2c @ hseg -> pw2, broadcast h, csync)
// kind 1: anchor cell  (partial = w1c @ hseg -> pw1, broadcast h, csync)
// kind 2: final cell   (local h,c only; no broadcast, no csync)
__device__ __forceinline__ void do_cell(Smem* s, int rank, int tid, int kind) {
    __syncthreads();
    const int lane = tid & 31, wrp = tid >> 5;

    // ---- G phase: 64 gate rows per CTA (gate q, elem rank*16 + j) ----
    {
        const float4* XV = (const float4*)s->x;
        const float4* HV = (const float4*)s->h;
        float4 xa = XV[lane], xb = XV[lane + 32];
        float4 ha = HV[lane], hb = HV[lane + 32];
#pragma unroll
        for (int rr = 0; rr < 8; rr++) {
            int r = wrp * 8 + rr;
            const float4* wi = (const float4*)(s->wih + r * LSTMN);
            const float4* wh = (const float4*)(s->whh + r * LSTMN);
            float4 a = wi[lane], b4 = wi[lane + 32];
            float acc = a.x * xa.x + a.y * xa.y + a.z * xa.z + a.w * xa.w
                      + b4.x * xb.x + b4.y * xb.y + b4.z * xb.z + b4.w * xb.w;
            a = wh[lane]; b4 = wh[lane + 32];
            acc += a.x * ha.x + a.y * ha.y + a.z * ha.z + a.w * ha.w
                 + b4.x * hb.x + b4.y * hb.y + b4.z * hb.z + b4.w * hb.w;
            acc += __shfl_xor_sync(0xffffffffu, acc, 16);
            acc += __shfl_xor_sync(0xffffffffu, acc, 8);
            acc += __shfl_xor_sync(0xffffffffu, acc, 4);
            acc += __shfl_xor_sync(0xffffffffu, acc, 2);
            acc += __shfl_xor_sync(0xffffffffu, acc, 1);
            if (lane == 0) s->g[r] = acc + s->bsum[r];
        }
    }
    __syncthreads();

    // ---- H phase: fully local (gates for own 16 elements live in own g) ----
    if (tid < 16) {
        int j = tid;
        float gi = s->g[j], gf = s->g[16 + j], gg = s->g[32 + j], go = s->g[48 + j];
        float cn = my_sig(gf) * s->c16[j] + my_sig(gi) * my_tanh(gg);
        float hn = my_sig(go) * my_tanh(cn);
        s->c16[j] = cn;
        s->hseg[j] = hn;
        if (kind != 2) {
            uint32_t ha = sm_u32(&s->h[rank * 16 + j]);
#pragma unroll
            for (int r = 0; r < CLSZ; r++) ds_st(ha, (uint32_t)r, hn);
        }
    }
    __syncthreads();

    if (kind != 2) {
        // ---- local partial matvec over own h segment ----
        const float* wc = (kind == 1 ? s->w1c : s->w2c) + tid * 16;
        float acc = 0.0f;
#pragma unroll
        for (int k = 0; k < 16; k++) acc = fmaf(wc[k], s->hseg[k], acc);
        if (kind == 1) s->pw1[tid] = acc; else s->pw2[tid] = acc;
        csync();   // h broadcast + partials visible cluster-wide
    }
}

// gather summed anchors_w1 slice for (layer l, half) CTAs serving slot
__device__ __forceinline__ void do_anchor_gather(Smem* s, int rank, int tid, int slot) {
    int half = rank >> 3, l = rank & 7;
    bool gat = (l == slot) || (slot == 0 && l == 1);
    if (gat && tid < 128) {
        uint32_t pa = sm_u32(&s->pw1[half * 128 + tid]);
        float a = 0.0f;
#pragma unroll
        for (int r = 0; r < CLSZ; r++) a += ds_ld(pa, (uint32_t)r);
        s->my_aw1[tid] = a;
    }
}

// ---------------- sampling ----------------
__device__ __forceinline__ void do_sample(Smem* s, int rank, int tid, int layer,
                                          uint2 bkey, int step, float* out, int b) {
    const int lane = tid & 31, wrp = tid >> 5;
    const int half = rank >> 3, l = rank & 7;

    // qv: CTA (l, half) computes its half of layer-l's logit
    if (l < layer && tid < 128) {
        uint32_t pa = sm_u32(&s->pw2[half * 128 + tid]);
        float a = 0.0f;
#pragma unroll
        for (int r = 0; r < CLSZ; r++) a += ds_ld(pa, (uint32_t)r);
        int e = half * 128 + tid;
        float val = my_tanh(s->my_aw1[tid] + a) * s->v[e];
        val += __shfl_xor_sync(0xffffffffu, val, 16);
        val += __shfl_xor_sync(0xffffffffu, val, 8);
        val += __shfl_xor_sync(0xffffffffu, val, 4);
        val += __shfl_xor_sync(0xffffffffu, val, 2);
        val += __shfl_xor_sync(0xffffffffu, val, 1);
        if (lane == 0) s->red[12 + wrp] = val;
    }
    __syncthreads();
    if (l < layer && tid == 0) {
        float p = s->red[12] + s->red[13] + s->red[14] + s->red[15];
        uint32_t ra = sm_u32(&s->red[2 * l + half]);
#pragma unroll
        for (int r = 0; r < CLSZ; r++) ds_st(ra, (uint32_t)r, p);
    }
    csync();   // partial logits visible everywhere

    // replicated Gumbel sampling (warp 0), all fp32 like JAX
    if (wrp == 0) {
        const bool act = lane < layer;
        float logit = 0.0f;
        if (act)
            logit = 1.1f * my_tanh((s->red[2 * lane] + s->red[2 * lane + 1]) * 0.2f);
        uint2 skey = tf2x32(bkey, make_uint2(0u, (uint32_t)step));
        float pert = -1e38f;
        if (act) {
            uint2 o = tf2x32(skey, make_uint2(0u, (uint32_t)lane));
            uint32_t bits = o.x ^ o.y;
            float u = __uint_as_float((bits >> 9) | 0x3f800000u) - 1.0f;
            const float TINYF = 1.17549435e-38f;
            float up = fmaxf(TINYF, u + TINYF);
            pert = -logf(-logf(up)) + logit;
        }
        float bp = pert; int bi = act ? lane : 64;
#pragma unroll
        for (int off = 16; off; off >>= 1) {
            float op = __shfl_xor_sync(0xffffffffu, bp, off);
            int oi = __shfl_xor_sync(0xffffffffu, bi, off);
            if (op > bp || (op == bp && oi < bi)) { bp = op; bi = oi; }
        }
        float lm = act ? logit : -1e38f;
#pragma unroll
        for (int off = 16; off; off >>= 1)
            lm = fmaxf(lm, __shfl_xor_sync(0xffffffffu, lm, off));
        float se = act ? expf(logit - lm) : 0.0f;
#pragma unroll
        for (int off = 16; off; off >>= 1)
            se += __shfl_xor_sync(0xffffffffu, se, off);
        float lse = logf(se);
        float ls = logit - lm - lse;
        float ls_best = __shfl_sync(0xffffffffu, ls, bi);
        float ec = act ? (-ls * expf(ls)) : 0.0f;
#pragma unroll
        for (int off = 16; off; off >>= 1)
            ec += __shfl_xor_sync(0xffffffffu, ec, off);
        if (lane == 0) {
            s->lp += -ls_best;
            s->ent += ec;
            s->idx = bi;
            if (rank == 0) out[b * 10 + step] = (float)bi;
        }
    }
    __syncthreads();
    s->x[tid] = s->anc[s->idx][tid];
}

// ---------------- main kernel ----------------
__global__ void __launch_bounds__(NTH, 1) ctrl_kernel(
    const float* __restrict__ enc_w, const float* __restrict__ w_ih,
    const float* __restrict__ w_hh, const float* __restrict__ b_ih,
    const float* __restrict__ b_hh, const float* __restrict__ w1,
    const float* __restrict__ w2, const float* __restrict__ v,
    float* __restrict__ out)
{
    extern __shared__ char smraw[];
    Smem* s = (Smem*)smraw;
    const int tid = threadIdx.x;
    const int rank = (int)ctarank();
    const int b = blockIdx.y;

    // ---- prologue ----
    {
        // w_ih / w_hh rows: local row lr -> global row (lr/16)*256 + rank*16 + lr%16
        for (int i = tid; i < 64 * 64; i += NTH) {
            int lr = i >> 6, pos = i & 63;
            int grow = ((lr >> 4) << 8) + rank * 16 + (lr & 15);
            ((float4*)s->wih)[i] = ((const float4*)w_ih)[grow * 64 + pos];
        }
        for (int i = tid; i < 64 * 64; i += NTH) {
            int lr = i >> 6, pos = i & 63;
            int grow = ((lr >> 4) << 8) + rank * 16 + (lr & 15);
            ((float4*)s->whh)[i] = ((const float4*)w_hh)[grow * 64 + pos];
        }
        // w1 / w2 columns [rank*16, rank*16+16) for all 256 rows
        {
            int j = tid;
            const float4* s1 = (const float4*)(w1 + j * 256 + rank * 16);
            const float4* s2 = (const float4*)(w2 + j * 256 + rank * 16);
            float4* d1 = (float4*)(s->w1c + j * 16);
            float4* d2 = (float4*)(s->w2c + j * 16);
#pragma unroll
            for (int k = 0; k < 4; k++) { d1[k] = s1[k]; d2[k] = s2[k]; }
        }
        if (tid < 64) {
            int grow = ((tid >> 4) << 8) + rank * 16 + (tid & 15);
            s->bsum[tid] = b_ih[grow] + b_hh[grow];
        }
        float e = enc_w[tid];
        s->enc0[tid] = e;
        s->x[tid] = e;
        s->v[tid] = v[tid];
        s->h[tid] = 0.0f;
        s->anc[0][tid] = 0.0f;
        s->anc[1][tid] = 0.0f;
        if (tid < 16) s->c16[tid] = 0.0f;
        if (tid == 0) { s->lp = 0.0f; s->ent = 0.0f; s->idx = 0; }
    }

    const uint2 key42 = make_uint2(0u, 42u);
    const uint2 bkey = tf2x32(key42, make_uint2(0u, (uint32_t)b));

    // first two reference layers = one identical zero-state cell -> aw1[0]=aw1[1]
    do_cell(s, rank, tid, 1);
    do_anchor_gather(s, rank, tid, 0);

    int step = 0;
#pragma unroll 1
    for (int layer = 2; layer <= 6; layer++) {
#pragma unroll 1
        for (int rep = 0; rep < 2; rep++) {
            do_cell(s, rank, tid, 0);
            do_sample(s, rank, tid, layer, bkey, step, out, b);
            step++;
        }
        if (layer < 6) {
            do_cell(s, rank, tid, 1);
            s->anc[layer][tid] = s->h[tid];
            do_anchor_gather(s, rank, tid, layer);
            s->x[tid] = s->enc0[tid];
        } else {
            do_cell(s, rank, tid, 2);   // final cell: local h,c only
        }
    }

    // ---- epilogue: deadlock-free last-cluster scalar reduction ----
    // Each cluster publishes its partials; the LAST cluster to arrive at the
    // atomic counter sums all partials in fixed order (deterministic) and
    // self-resets the counter for the next graph replay. No spin-waiting on
    // other clusters -> no co-residency requirement.
    if (rank == 0 && tid == 0) {
        g_lp[b] = s->lp;
        g_ent[b] = s->ent;
        __threadfence();
        int prev = atomicAdd(&g_count, 1);
        if (prev == NBLK - 1) {
            __threadfence();
            float slp = 0.0f, sent = 0.0f;
#pragma unroll
            for (int bb = 0; bb < NBLK; bb++) {
                slp += ((volatile float*)g_lp)[bb];
                sent += ((volatile float*)g_ent)[bb];
            }
            out[60] = slp;
            out[61] = sent;
            g_count = 0;   // reset for graph replay
        }
    }
    if (b == NBLK - 1 && tid < 16) {
        out[62 + rank * 16 + tid] = s->c16[tid];
        out[62 + 256 + rank * 16 + tid] = s->hseg[tid];
    }
}

extern "C" void kernel_launch(void* const* d_in, const int* in_sizes, int n_in,
                              void* d_out, int out_size) {
    const float* enc_w = (const float*)d_in[0];
    const float* w_ih  = (const float*)d_in[1];
    const float* w_hh  = (const float*)d_in[2];
    const float* b_ih  = (const float*)d_in[3];
    const float* b_hh  = (const float*)d_in[4];
    const float* w1    = (const float*)d_in[5];
    const float* w2    = (const float*)d_in[6];
    const float* v     = (const float*)d_in[7];
    float* out = (float*)d_out;

    cudaFuncSetAttribute(ctrl_kernel,
                         cudaFuncAttributeMaxDynamicSharedMemorySize,
                         (int)sizeof(Smem));
    cudaFuncSetAttribute(ctrl_kernel,
                         cudaFuncAttributeNonPortableClusterSizeAllowed, 1);

    cudaLaunchConfig_t cfg = {};
    cfg.gridDim = dim3(CLSZ, NBLK, 1);
    cfg.blockDim = dim3(NTH, 1, 1);
    cfg.dynamicSmemBytes = sizeof(Smem);
    cfg.stream = 0;
    cudaLaunchAttribute at[1];
    at[0].id = cudaLaunchAttributeClusterDimension;
    at[0].val.clusterDim.x = CLSZ;
    at[0].val.clusterDim.y = 1;
    at[0].val.clusterDim.z = 1;
    cfg.attrs = at;
    cfg.numAttrs = 1;

    cudaLaunchKernelEx(&cfg, ctrl_kernel,
                       enc_w, w_ih, w_hh, b_ih, b_hh, w1, w2, v, out);
}